// round 7
// baseline (speedup 1.0000x reference)
#include <cuda_runtime.h>
#include <cuda_fp16.h>

// CSWin attention: B=2, H=64, W=64, N=4, DIM=128, HEADS=4, SPLIT=2
// 64 windows, L=512 tokens/window, head_dim=32, 4 heads.
// Token t: hh = t>>3, ww = (t>>2)&1, nn = t&3 ; spatial group sp = t>>2.

#define FULLMASK 0xffffffffu
#define KST2 20       // u32 stride of Ku rows: banks 20g+t -> conflict-free
#define VTSTR 260     // u32 stride of VT rows: banks 4g+t -> conflict-free
#define VSUMSTR 33

__device__ __forceinline__ int goff(int b, int hh, int wd, int nn, int c) {
    return (((b * 64 + hh) * 64 + wd) * 4 + nn) * 128 + c;
}

__device__ __forceinline__ float ex2(float x) {
    float r;
    asm("ex2.approx.f32 %0, %1;" : "=f"(r) : "f"(x));
    return r;
}

__device__ __forceinline__ unsigned h2u(__half2 h) {
    return *reinterpret_cast<unsigned*>(&h);
}
__device__ __forceinline__ __half2 uh2(unsigned u) {
    return *reinterpret_cast<__half2*>(&u);
}

// D += A(16x16,f16) * B(16x8,f16), row.col, f32 accum
__device__ __forceinline__ void mma_f16(float c[4], unsigned a0, unsigned a1,
                                        unsigned a2, unsigned a3,
                                        unsigned b0, unsigned b1) {
    asm volatile(
        "mma.sync.aligned.m16n8k16.row.col.f32.f16.f16.f32 "
        "{%0,%1,%2,%3}, {%4,%5,%6,%7}, {%8,%9}, {%0,%1,%2,%3};\n"
        : "+f"(c[0]), "+f"(c[1]), "+f"(c[2]), "+f"(c[3])
        : "r"(a0), "r"(a1), "r"(a2), "r"(a3), "r"(b0), "r"(b1));
}

// ---------------------------------------------------------------------------
// Fused flash attention + RPE, all-fp16 MMA. One CTA per (window, head),
// 1024 threads = 32 warps, 16 rows per warp (one m16 tile).
// smem: Ku[512][20] u32 (K fp16 channel-pairs per token)
//     + VT[40][260] u32 (V fp16 token-pairs per channel; row 32 = ones,
//       rows 33-39 = zeros for the tensor-core row-sum trick) + CW[288].
// Q fragments load straight from gmem (no Q smem). P stays in registers:
// QK C-fragments repack directly into fp16 A-fragments for PV.
// Ku region is reused for Vsum in the RPE epilogue.
// ---------------------------------------------------------------------------
__global__ __launch_bounds__(1024, 1)
void cswin_fused(const float* __restrict__ q, const float* __restrict__ k,
                 const float* __restrict__ v, const float* __restrict__ cw,
                 float* __restrict__ out)
{
    extern __shared__ unsigned smu[];
    unsigned* Ku  = smu;                          // 512*20 u32
    unsigned* VTu = smu + 512 * KST2;             // 40*260 u32
    __half*   VT16 = (__half*)VTu;                // [40][520] halves
    float*    CWs = (float*)(smu + 512 * KST2 + 40 * VTSTR); // 288 floats
    float*    Vsum = (float*)Ku;                  // reused after main loop

    const float NEG_INF = __int_as_float(0xff800000);
    const float SCL = 0.25500766198160955f; // (1/sqrt(32)) * log2(e)

    int bx = blockIdx.x;
    int win = bx >> 2, h = bx & 3;
    int b = win >> 5, jw = win & 31;
    int cbase = h * 32;
    int tid = threadIdx.x, warp = tid >> 5, lane = tid & 31;
    int g = lane >> 2, t = lane & 3;

    // ---- conv weight slice for this head ----
    if (tid < 288) CWs[tid] = cw[cbase * 9 + tid];

    // ---- ones / zeros rows of VT (d = 32..39) ----
    for (int e = tid; e < 8 * VTSTR; e += 1024) {
        int d = 32 + e / VTSTR, jp = e % VTSTR;
        VTu[d * VTSTR + jp] = (d == 32) ? 0x3C003C00u : 0u;
    }

    // ---- stage K (fp16 pairs) and V (fp16 transposed): 2 threads per token ----
    {
        int tok = tid >> 1, hs = tid & 1;
        int hh = tok >> 3, ww = (tok >> 2) & 1, nn = tok & 3;
        int ga = goff(b, hh, jw * 2 + ww, nn, cbase + 16 * hs);
        float4 k0 = *(const float4*)(k + ga);
        float4 k1 = *(const float4*)(k + ga + 4);
        float4 k2 = *(const float4*)(k + ga + 8);
        float4 k3 = *(const float4*)(k + ga + 12);
        unsigned* kd = Ku + tok * KST2 + 8 * hs;
        kd[0] = h2u(__floats2half2_rn(k0.x, k0.y));
        kd[1] = h2u(__floats2half2_rn(k0.z, k0.w));
        kd[2] = h2u(__floats2half2_rn(k1.x, k1.y));
        kd[3] = h2u(__floats2half2_rn(k1.z, k1.w));
        kd[4] = h2u(__floats2half2_rn(k2.x, k2.y));
        kd[5] = h2u(__floats2half2_rn(k2.z, k2.w));
        kd[6] = h2u(__floats2half2_rn(k3.x, k3.y));
        kd[7] = h2u(__floats2half2_rn(k3.z, k3.w));
        float4 v0 = *(const float4*)(v + ga);
        float4 v1 = *(const float4*)(v + ga + 4);
        float4 v2 = *(const float4*)(v + ga + 8);
        float4 v3 = *(const float4*)(v + ga + 12);
        int dbase = 16 * hs;
        VT16[(dbase + 0) * 520 + tok]  = __float2half(v0.x);
        VT16[(dbase + 1) * 520 + tok]  = __float2half(v0.y);
        VT16[(dbase + 2) * 520 + tok]  = __float2half(v0.z);
        VT16[(dbase + 3) * 520 + tok]  = __float2half(v0.w);
        VT16[(dbase + 4) * 520 + tok]  = __float2half(v1.x);
        VT16[(dbase + 5) * 520 + tok]  = __float2half(v1.y);
        VT16[(dbase + 6) * 520 + tok]  = __float2half(v1.z);
        VT16[(dbase + 7) * 520 + tok]  = __float2half(v1.w);
        VT16[(dbase + 8) * 520 + tok]  = __float2half(v2.x);
        VT16[(dbase + 9) * 520 + tok]  = __float2half(v2.y);
        VT16[(dbase + 10) * 520 + tok] = __float2half(v2.z);
        VT16[(dbase + 11) * 520 + tok] = __float2half(v2.w);
        VT16[(dbase + 12) * 520 + tok] = __float2half(v3.x);
        VT16[(dbase + 13) * 520 + tok] = __float2half(v3.y);
        VT16[(dbase + 14) * 520 + tok] = __float2half(v3.z);
        VT16[(dbase + 15) * 520 + tok] = __float2half(v3.w);
    }
    __syncthreads();

    // ---- Q fragments straight from gmem (fp16, scale+log2e folded in) ----
    int r0 = warp * 16;
    unsigned qf[2][4];   // [ks: k16 step][a-reg]
    #pragma unroll
    for (int ks = 0; ks < 2; ks++)
        #pragma unroll
        for (int rr = 0; rr < 2; rr++) {
            int row = r0 + g + rr * 8;
            int ga = goff(b, row >> 3, jw * 2 + ((row >> 2) & 1), row & 3,
                          cbase + 16 * ks + 2 * t);
            float2 lo = *(const float2*)(q + ga);
            float2 hi = *(const float2*)(q + ga + 8);
            qf[ks][rr]     = h2u(__floats2half2_rn(lo.x * SCL, lo.y * SCL));
            qf[ks][rr + 2] = h2u(__floats2half2_rn(hi.x * SCL, hi.y * SCL));
        }

    float O[4][4];
    float Osum[4];
    #pragma unroll
    for (int nt = 0; nt < 4; nt++)
        #pragma unroll
        for (int r = 0; r < 4; r++) O[nt][r] = 0.f;
    #pragma unroll
    for (int r = 0; r < 4; r++) Osum[r] = 0.f;

    #pragma unroll 1
    for (int c = 0; c < 16; c++) {
        int j0 = c * 32;
        bool diag = (c == (warp >> 1));
        unsigned ph[4][2];

        // S tile per nt: compute, mask, exp2, pack -- S stays transient.
        #pragma unroll
        for (int nt = 0; nt < 4; nt++) {
            float S4[4] = {0.f, 0.f, 0.f, 0.f};
            #pragma unroll
            for (int ks = 0; ks < 2; ks++) {
                const unsigned* kp = Ku + (j0 + nt * 8 + g) * KST2 + ks * 8 + t;
                mma_f16(S4, qf[ks][0], qf[ks][1], qf[ks][2], qf[ks][3],
                        kp[0], kp[4]);
            }
            if (diag) {
                #pragma unroll
                for (int r = 0; r < 4; r++) {
                    int i = r0 + g + ((r >> 1) ? 8 : 0);
                    int j = j0 + nt * 8 + 2 * t + (r & 1);
                    if (((i >> 2) == (j >> 2)) && (i != j)) S4[r] = NEG_INF;
                }
            }
            ph[nt][0] = h2u(__floats2half2_rn(ex2(S4[0]), ex2(S4[1])));
            ph[nt][1] = h2u(__floats2half2_rn(ex2(S4[2]), ex2(S4[3])));
        }

        // O += P * V (vt=4 is the ones-column -> row sums)
        #pragma unroll
        for (int kc = 0; kc < 2; kc++) {
            int vb = (j0 >> 1) + kc * 8 + t;
            #pragma unroll
            for (int vt = 0; vt < 5; vt++) {
                const unsigned* vp = VTu + (vt * 8 + g) * VTSTR + vb;
                float* dst = (vt < 4) ? O[vt] : Osum;
                mma_f16(dst, ph[2 * kc][0], ph[2 * kc][1],
                             ph[2 * kc + 1][0], ph[2 * kc + 1][1],
                        vp[0], vp[4]);
            }
        }
    }

    // ---- row sums sit in Osum (col 32 -> t==0 lanes, c0/c2) ----
    float inv[2];
    {
        float l0 = __shfl_sync(FULLMASK, Osum[0], lane & ~3);
        float l1 = __shfl_sync(FULLMASK, Osum[2], lane & ~3);
        inv[0] = 1.0f / l0;
        inv[1] = 1.0f / l1;
    }

    // ---- build Vsum[sp][c] in the freed K region ----
    __syncthreads();
    for (int e = tid; e < 4096; e += 1024) {
        int sp = e >> 5, cc = e & 31;
        unsigned u0 = VTu[cc * VTSTR + sp * 2];
        unsigned u1 = VTu[cc * VTSTR + sp * 2 + 1];
        float2 f0 = __half22float2(uh2(u0));
        float2 f1 = __half22float2(uh2(u1));
        Vsum[sp * VSUMSTR + cc] = f0.x + f0.y + f1.x + f1.y;
    }
    __syncthreads();

    // ---- epilogue: out = O/l + rpe ----
    #pragma unroll
    for (int nt = 0; nt < 4; nt++) {
        int c0 = nt * 8 + 2 * t;   // channel within head
        #pragma unroll
        for (int half = 0; half < 2; half++) {
            int i = r0 + g + half * 8;
            int sp = i >> 2;
            int hh = sp >> 1, ww = sp & 1;
            float2 val;
            val.x = O[nt][half * 2 + 0] * inv[half];
            val.y = O[nt][half * 2 + 1] * inv[half];
            #pragma unroll
            for (int cc = 0; cc < 2; cc++) {
                int ch = c0 + cc;
                const float* wc = CWs + ch * 9;
                float acc = 0.f;
                #pragma unroll
                for (int ky = 0; ky < 3; ky++) {
                    int h2 = hh + ky - 1;
                    if (h2 < 0 || h2 >= 64) continue;
                    #pragma unroll
                    for (int kx = 0; kx < 3; kx++) {
                        int w2 = ww + kx - 1;
                        if (w2 < 0 || w2 >= 2) continue;
                        acc += wc[ky * 3 + kx] * Vsum[(h2 * 2 + w2) * VSUMSTR + ch];
                    }
                }
                float center = wc[4];
                float vi = __half2float(VT16[ch * 520 + i]);
                float rpe = acc - center * (Vsum[sp * VSUMSTR + ch] - vi);
                if (cc == 0) val.x += rpe; else val.y += rpe;
            }
            int ga = goff(b, i >> 3, jw * 2 + ((i >> 2) & 1), i & 3, cbase + c0);
            *(float2*)(out + ga) = val;
        }
    }
}

extern "C" void kernel_launch(void* const* d_in, const int* in_sizes, int n_in,
                              void* d_out, int out_size)
{
    const float* q  = (const float*)d_in[0];
    const float* k  = (const float*)d_in[1];
    const float* v  = (const float*)d_in[2];
    const float* cw = (const float*)d_in[3];
    float* out = (float*)d_out;

    const int SMEM = (512 * KST2 + 40 * VTSTR + 288) * 4;  // 83712 B

    cudaFuncSetAttribute(cswin_fused,
                         cudaFuncAttributeMaxDynamicSharedMemorySize, SMEM);
    cswin_fused<<<256, 1024, SMEM>>>(q, k, v, cw, out);
}

// round 8
// speedup vs baseline: 1.5854x; 1.5854x over previous
#include <cuda_runtime.h>
#include <cuda_fp16.h>

// CSWin attention: B=2, H=64, W=64, N=4, DIM=128, HEADS=4, SPLIT=2
// 64 windows, L=512 tokens/window, head_dim=32, 4 heads.
// Token t: hh = t>>3, ww = (t>>2)&1, nn = t&3 ; spatial group sp = t>>2.

#define FULLMASK 0xffffffffu
#define KST2 20       // u32 stride of Ku rows: banks 20g+t -> conflict-free
#define VTSTR 260     // u32 stride of VT rows: banks 4g+t -> conflict-free
#define VSUMSTR 33

__device__ __forceinline__ int goff(int b, int hh, int wd, int nn, int c) {
    return (((b * 64 + hh) * 64 + wd) * 4 + nn) * 128 + c;
}

__device__ __forceinline__ float ex2(float x) {
    float r;
    asm("ex2.approx.f32 %0, %1;" : "=f"(r) : "f"(x));
    return r;
}

__device__ __forceinline__ unsigned h2u(__half2 h) {
    return *reinterpret_cast<unsigned*>(&h);
}
__device__ __forceinline__ __half2 uh2(unsigned u) {
    return *reinterpret_cast<__half2*>(&u);
}

// D += A(16x16,f16) * B(16x8,f16), row.col, f32 accum
__device__ __forceinline__ void mma_f16(float c[4], unsigned a0, unsigned a1,
                                        unsigned a2, unsigned a3,
                                        unsigned b0, unsigned b1) {
    asm volatile(
        "mma.sync.aligned.m16n8k16.row.col.f32.f16.f16.f32 "
        "{%0,%1,%2,%3}, {%4,%5,%6,%7}, {%8,%9}, {%0,%1,%2,%3};\n"
        : "+f"(c[0]), "+f"(c[1]), "+f"(c[2]), "+f"(c[3])
        : "r"(a0), "r"(a1), "r"(a2), "r"(a3), "r"(b0), "r"(b1));
}

// ---------------------------------------------------------------------------
// Fused flash attention + RPE, all-fp16 MMA. One CTA per (window, head),
// 512 threads = 16 warps, 32 rows per warp (two m16 tiles -> B-frag reuse).
// smem: Ku[512][20] u32 (K fp16 channel-pairs per token)
//     + VT[40][260] u32 (V fp16 token-pairs per channel; row 32 = ones,
//       rows 33-39 = zeros for the tensor-core row-sum trick) + CW[288].
// Q fragments load straight from gmem. P stays in registers: QK C-fragments
// repack directly into fp16 A-fragments for PV. Row sums come from the
// ones-column. Ku region is reused for Vsum in the RPE epilogue.
// ---------------------------------------------------------------------------
__global__ __launch_bounds__(512, 1)
void cswin_fused(const float* __restrict__ q, const float* __restrict__ k,
                 const float* __restrict__ v, const float* __restrict__ cw,
                 float* __restrict__ out)
{
    extern __shared__ unsigned smu[];
    unsigned* Ku  = smu;                          // 512*20 u32
    unsigned* VTu = smu + 512 * KST2;             // 40*260 u32
    __half*   VT16 = (__half*)VTu;                // [40][520] halves
    float*    CWs = (float*)(smu + 512 * KST2 + 40 * VTSTR); // 288 floats
    float*    Vsum = (float*)Ku;                  // reused after main loop

    const float NEG_INF = __int_as_float(0xff800000);
    const float SCL = 0.25500766198160955f; // (1/sqrt(32)) * log2(e)

    int bx = blockIdx.x;
    int win = bx >> 2, h = bx & 3;
    int b = win >> 5, jw = win & 31;
    int cbase = h * 32;
    int tid = threadIdx.x, warp = tid >> 5, lane = tid & 31;
    int g = lane >> 2, t = lane & 3;

    // ---- conv weight slice for this head ----
    if (tid < 288) CWs[tid] = cw[cbase * 9 + tid];

    // ---- ones / zeros rows of VT (d = 32..39) ----
    for (int e = tid; e < 8 * VTSTR; e += 512) {
        int d = 32 + e / VTSTR, jp = e % VTSTR;
        VTu[d * VTSTR + jp] = (d == 32) ? 0x3C003C00u : 0u;
    }

    // ---- stage K (fp16 pairs) and V (fp16 transposed): 1 thread per token ----
    {
        int tok = tid;
        int hh = tok >> 3, ww = (tok >> 2) & 1, nn = tok & 3;
        int ga = goff(b, hh, jw * 2 + ww, nn, cbase);
        unsigned* kd = Ku + tok * KST2;
        #pragma unroll
        for (int cc8 = 0; cc8 < 4; cc8++) {
            float4 k0 = *(const float4*)(k + ga + cc8 * 8);
            float4 k1 = *(const float4*)(k + ga + cc8 * 8 + 4);
            kd[cc8 * 4 + 0] = h2u(__floats2half2_rn(k0.x, k0.y));
            kd[cc8 * 4 + 1] = h2u(__floats2half2_rn(k0.z, k0.w));
            kd[cc8 * 4 + 2] = h2u(__floats2half2_rn(k1.x, k1.y));
            kd[cc8 * 4 + 3] = h2u(__floats2half2_rn(k1.z, k1.w));
            float4 v0 = *(const float4*)(v + ga + cc8 * 8);
            float4 v1 = *(const float4*)(v + ga + cc8 * 8 + 4);
            VT16[(cc8 * 8 + 0) * 520 + tok] = __float2half(v0.x);
            VT16[(cc8 * 8 + 1) * 520 + tok] = __float2half(v0.y);
            VT16[(cc8 * 8 + 2) * 520 + tok] = __float2half(v0.z);
            VT16[(cc8 * 8 + 3) * 520 + tok] = __float2half(v0.w);
            VT16[(cc8 * 8 + 4) * 520 + tok] = __float2half(v1.x);
            VT16[(cc8 * 8 + 5) * 520 + tok] = __float2half(v1.y);
            VT16[(cc8 * 8 + 6) * 520 + tok] = __float2half(v1.z);
            VT16[(cc8 * 8 + 7) * 520 + tok] = __float2half(v1.w);
        }
    }
    __syncthreads();

    // ---- Q fragments straight from gmem (fp16, scale+log2e folded in) ----
    int r0 = warp * 32;
    unsigned qf[2][2][4];   // [mt][ks][a-reg]
    #pragma unroll
    for (int mt = 0; mt < 2; mt++)
        #pragma unroll
        for (int ks = 0; ks < 2; ks++)
            #pragma unroll
            for (int rr = 0; rr < 2; rr++) {
                int row = r0 + mt * 16 + g + rr * 8;
                int ga = goff(b, row >> 3, jw * 2 + ((row >> 2) & 1), row & 3,
                              cbase + 16 * ks + 2 * t);
                float2 lo = *(const float2*)(q + ga);
                float2 hi = *(const float2*)(q + ga + 8);
                qf[mt][ks][rr]     = h2u(__floats2half2_rn(lo.x * SCL, lo.y * SCL));
                qf[mt][ks][rr + 2] = h2u(__floats2half2_rn(hi.x * SCL, hi.y * SCL));
            }

    float O[2][4][4];
    float Osum[2][4];
    #pragma unroll
    for (int mt = 0; mt < 2; mt++) {
        #pragma unroll
        for (int nt = 0; nt < 4; nt++)
            #pragma unroll
            for (int r = 0; r < 4; r++) O[mt][nt][r] = 0.f;
        #pragma unroll
        for (int r = 0; r < 4; r++) Osum[mt][r] = 0.f;
    }

    #pragma unroll 1
    for (int c = 0; c < 16; c++) {
        int j0 = c * 32;
        bool diag = (c == warp);
        unsigned ph[2][4][2];

        // S tiles: compute, mask, exp2, pack -- S stays transient per nt.
        #pragma unroll
        for (int nt = 0; nt < 4; nt++) {
            float S0[4] = {0.f, 0.f, 0.f, 0.f};
            float S1[4] = {0.f, 0.f, 0.f, 0.f};
            #pragma unroll
            for (int ks = 0; ks < 2; ks++) {
                const unsigned* kp = Ku + (j0 + nt * 8 + g) * KST2 + ks * 8 + t;
                unsigned b0 = kp[0], b1 = kp[4];
                mma_f16(S0, qf[0][ks][0], qf[0][ks][1], qf[0][ks][2], qf[0][ks][3], b0, b1);
                mma_f16(S1, qf[1][ks][0], qf[1][ks][1], qf[1][ks][2], qf[1][ks][3], b0, b1);
            }
            if (diag) {
                #pragma unroll
                for (int r = 0; r < 4; r++) {
                    int j = j0 + nt * 8 + 2 * t + (r & 1);
                    int i0 = r0 + g + ((r >> 1) ? 8 : 0);
                    int i1 = i0 + 16;
                    if (((i0 >> 2) == (j >> 2)) && (i0 != j)) S0[r] = NEG_INF;
                    if (((i1 >> 2) == (j >> 2)) && (i1 != j)) S1[r] = NEG_INF;
                }
            }
            ph[0][nt][0] = h2u(__floats2half2_rn(ex2(S0[0]), ex2(S0[1])));
            ph[0][nt][1] = h2u(__floats2half2_rn(ex2(S0[2]), ex2(S0[3])));
            ph[1][nt][0] = h2u(__floats2half2_rn(ex2(S1[0]), ex2(S1[1])));
            ph[1][nt][1] = h2u(__floats2half2_rn(ex2(S1[2]), ex2(S1[3])));
        }

        // O += P * V (vt=4 is the ones-column -> row sums)
        #pragma unroll
        for (int kc = 0; kc < 2; kc++) {
            int vb = (j0 >> 1) + kc * 8 + t;
            #pragma unroll
            for (int vt = 0; vt < 5; vt++) {
                const unsigned* vp = VTu + (vt * 8 + g) * VTSTR + vb;
                unsigned b0 = vp[0], b1 = vp[4];
                float* d0 = (vt < 4) ? O[0][vt] : Osum[0];
                float* d1 = (vt < 4) ? O[1][vt] : Osum[1];
                mma_f16(d0, ph[0][2 * kc][0], ph[0][2 * kc][1],
                            ph[0][2 * kc + 1][0], ph[0][2 * kc + 1][1], b0, b1);
                mma_f16(d1, ph[1][2 * kc][0], ph[1][2 * kc][1],
                            ph[1][2 * kc + 1][0], ph[1][2 * kc + 1][1], b0, b1);
            }
        }
    }

    // ---- row sums sit in Osum (col 32 -> t==0 lanes, c0/c2) ----
    float inv[4];
    #pragma unroll
    for (int mt = 0; mt < 2; mt++) {
        float l0 = __shfl_sync(FULLMASK, Osum[mt][0], lane & ~3);
        float l1 = __shfl_sync(FULLMASK, Osum[mt][2], lane & ~3);
        inv[mt * 2 + 0] = 1.0f / l0;
        inv[mt * 2 + 1] = 1.0f / l1;
    }

    // ---- build Vsum[sp][c] in the freed K region ----
    __syncthreads();
    for (int e = tid; e < 4096; e += 512) {
        int sp = e >> 5, cc = e & 31;
        unsigned u0 = VTu[cc * VTSTR + sp * 2];
        unsigned u1 = VTu[cc * VTSTR + sp * 2 + 1];
        float2 f0 = __half22float2(uh2(u0));
        float2 f1 = __half22float2(uh2(u1));
        Vsum[sp * VSUMSTR + cc] = f0.x + f0.y + f1.x + f1.y;
    }
    __syncthreads();

    // ---- epilogue: out = O/l + rpe ----
    #pragma unroll
    for (int mt = 0; mt < 2; mt++)
        #pragma unroll
        for (int nt = 0; nt < 4; nt++) {
            int c0 = nt * 8 + 2 * t;   // channel within head
            #pragma unroll
            for (int half = 0; half < 2; half++) {
                int i = r0 + mt * 16 + g + half * 8;
                int sp = i >> 2;
                int hh = sp >> 1, ww = sp & 1;
                float2 val;
                val.x = O[mt][nt][half * 2 + 0] * inv[mt * 2 + half];
                val.y = O[mt][nt][half * 2 + 1] * inv[mt * 2 + half];
                #pragma unroll
                for (int cc = 0; cc < 2; cc++) {
                    int ch = c0 + cc;
                    const float* wc = CWs + ch * 9;
                    float acc = 0.f;
                    #pragma unroll
                    for (int ky = 0; ky < 3; ky++) {
                        int h2 = hh + ky - 1;
                        if (h2 < 0 || h2 >= 64) continue;
                        #pragma unroll
                        for (int kx = 0; kx < 3; kx++) {
                            int w2 = ww + kx - 1;
                            if (w2 < 0 || w2 >= 2) continue;
                            acc += wc[ky * 3 + kx] * Vsum[(h2 * 2 + w2) * VSUMSTR + ch];
                        }
                    }
                    float center = wc[4];
                    float vi = __half2float(VT16[ch * 520 + i]);
                    float rpe = acc - center * (Vsum[sp * VSUMSTR + ch] - vi);
                    if (cc == 0) val.x += rpe; else val.y += rpe;
                }
                int ga = goff(b, i >> 3, jw * 2 + ((i >> 2) & 1), i & 3, cbase + c0);
                *(float2*)(out + ga) = val;
            }
        }
}

extern "C" void kernel_launch(void* const* d_in, const int* in_sizes, int n_in,
                              void* d_out, int out_size)
{
    const float* q  = (const float*)d_in[0];
    const float* k  = (const float*)d_in[1];
    const float* v  = (const float*)d_in[2];
    const float* cw = (const float*)d_in[3];
    float* out = (float*)d_out;

    const int SMEM = (512 * KST2 + 40 * VTSTR + 288) * 4;  // 83712 B

    cudaFuncSetAttribute(cswin_fused,
                         cudaFuncAttributeMaxDynamicSharedMemorySize, SMEM);
    cswin_fused<<<256, 512, SMEM>>>(q, k, v, cw, out);
}